// round 5
// baseline (speedup 1.0000x reference)
#include <cuda_runtime.h>
#include <math.h>

#define T_STEPS 128
#define NN 32
#define EE 512
#define INC 64
#define HID 128
#define SEQL 16
#define G4 512          // 4*HID
#define WPC 16          // windows per LSTM CTA (8 per half-block)
#define PPAD 144        // padded G1 rows (need 143 = T + SEQL - 1)
#define HS 20           // lstm smem row stride (floats): 16B-aligned
#define HSG 36          // g1 smem row stride (32 windows + pad, 16B-aligned)
#define WROW 1024       // pre-splat weight row stride in floats (G4*2)

typedef unsigned long long ull;

// ---------------- global scratch (no allocation allowed) ----------------
__device__ float d_H[T_STEPS * NN * HID];           // GCN output  [t][n][k]
__device__ float d_G1[NN * PPAD * G4];              // [n][p][4*k+g]
// pre-splatted LSTM weights: [n][kk][8*k + 2*g + {0,1}], value duplicated
__device__ float d_Wih1T[NN * HID * WROW];
__device__ float d_Whh1T[NN * HID * WROW];
__device__ float d_Wih2T[NN * HID * WROW];
__device__ float d_Whh2T[NN * HID * WROW];
__device__ float d_WfcT[NN * HID * HID];            // [n][h][k2]

// ---------------- f32x2 packed helpers ----------------------------------
__device__ __forceinline__ void ffma2(ull &d, ull a, ull b) {
    asm("fma.rn.f32x2 %0, %1, %2, %0;" : "+l"(d) : "l"(a), "l"(b));
}
__device__ __forceinline__ ull splat2(float x) {
    ull r; unsigned u = __float_as_uint(x);
    asm("mov.b64 %0, {%1, %1};" : "=l"(r) : "r"(u)); return r;
}
__device__ __forceinline__ ull pack2(float x, float y) {
    ull r; unsigned a = __float_as_uint(x), b = __float_as_uint(y);
    asm("mov.b64 %0, {%1, %2};" : "=l"(r) : "r"(a), "r"(b)); return r;
}
__device__ __forceinline__ float2 unpack2(ull v) {
    unsigned a, b;
    asm("mov.b64 {%0, %1}, %2;" : "=r"(a), "=r"(b) : "l"(v));
    return make_float2(__uint_as_float(a), __uint_as_float(b));
}

// ---------------- fast transcendentals (rel err ~1e-6, tol 1e-3) --------
__device__ __forceinline__ float sigf(float x) {
    return __fdividef(1.0f, 1.0f + __expf(-x));
}
__device__ __forceinline__ float tanh_f(float x) {
    float ax = fabsf(x);
    float e  = __expf(-2.0f * ax);             // in (0,1], no overflow
    float t  = __fdividef(1.0f - e, 1.0f + e);
    return copysignf(t, x);
}

// ---------------- weight transposes (pre-splatted for LSTM mats) --------
// dst[n][kk*1024 + 8*(j&127) + 2*(j>>7) + {0,1}] = src[n][j][kk]  (dup)
__global__ void transpose_kernel(const float* __restrict__ Wih1,
                                 const float* __restrict__ Whh1,
                                 const float* __restrict__ Wih2,
                                 const float* __restrict__ Whh2,
                                 const float* __restrict__ Wfc) {
    int n = blockIdx.x, m = blockIdx.y;
    __shared__ float s[32][33];
    int tx = threadIdx.x & 31, ty = threadIdx.x >> 5;   // 256 threads
    if (m == 4) {
        const float* src = Wfc + (size_t)n * HID * HID;
        float* dst = d_WfcT + (size_t)n * HID * HID;
        for (int bi = 0; bi < HID; bi += 32)
            for (int bj = 0; bj < HID; bj += 32) {
                #pragma unroll
                for (int r = ty; r < 32; r += 8)
                    s[r][tx] = src[(bi + r) * HID + bj + tx];
                __syncthreads();
                #pragma unroll
                for (int r = ty; r < 32; r += 8)
                    dst[(bj + r) * HID + bi + tx] = s[tx][r];
                __syncthreads();
            }
        return;
    }
    const float* src;
    float* dst;
    if      (m == 0) { src = Wih1; dst = d_Wih1T; }
    else if (m == 1) { src = Whh1; dst = d_Whh1T; }
    else if (m == 2) { src = Wih2; dst = d_Wih2T; }
    else             { src = Whh2; dst = d_Whh2T; }
    src += (size_t)n * G4 * HID; dst += (size_t)n * HID * WROW;
    for (int bj = 0; bj < G4; bj += 32) {       // j blocks
        for (int bi = 0; bi < HID; bi += 32) {  // kk blocks
            #pragma unroll
            for (int r = ty; r < 32; r += 8)
                s[r][tx] = src[(bj + r) * HID + bi + tx];
            __syncthreads();
            #pragma unroll
            for (int r = ty; r < 32; r += 8) {
                int j = bj + tx;
                float v = s[tx][r];
                int base = (bi + r) * WROW + 8 * (j & 127) + 2 * (j >> 7);
                dst[base] = v; dst[base + 1] = v;
            }
            __syncthreads();
        }
    }
}

// ---------------- per-timestep 2-layer GCN ------------------------------
__global__ __launch_bounds__(128) void gcn_kernel(
    const float* __restrict__ x, const int* __restrict__ ei,
    const float* __restrict__ W1, const float* __restrict__ b1,
    const float* __restrict__ W2, const float* __restrict__ b2) {
    int t = blockIdx.x, k = threadIdx.x;
    __shared__ float xs[NN * INC];
    __shared__ float A[NN * NN];
    __shared__ float dinv[NN];
    __shared__ float h0s[NN * HID];
    __shared__ float h1s[NN * HID];

    for (int i = k; i < NN * INC; i += 128) xs[i] = x[t * NN * INC + i];
    for (int i = k; i < NN * NN; i += 128)  A[i] = 0.f;
    if (k < NN) dinv[k] = 1.0f;
    __syncthreads();

    const int* row = ei + t * 2 * EE;
    const int* col = row + EE;
    for (int e = k; e < EE; e += 128) atomicAdd(&dinv[col[e]], 1.0f);
    __syncthreads();
    if (k < NN) dinv[k] = rsqrtf(dinv[k]);
    __syncthreads();
    for (int e = k; e < EE; e += 128) {
        int r = row[e], c = col[e];
        atomicAdd(&A[c * NN + r], dinv[r] * dinv[c]);
    }
    if (k < NN) atomicAdd(&A[k * NN + k], dinv[k] * dinv[k]);
    __syncthreads();

    float acc[NN];
    #pragma unroll
    for (int nn = 0; nn < NN; nn++) acc[nn] = 0.f;
    for (int c = 0; c < INC; c++) {
        float wv = W1[c * HID + k];
        #pragma unroll
        for (int nn = 0; nn < NN; nn++) acc[nn] += xs[nn * INC + c] * wv;
    }
    #pragma unroll
    for (int nn = 0; nn < NN; nn++) h0s[nn * HID + k] = acc[nn];
    __syncthreads();
    float bv = b1[k];
    #pragma unroll
    for (int nn = 0; nn < NN; nn++) {
        float s = bv;
        #pragma unroll
        for (int r = 0; r < NN; r++) s += A[nn * NN + r] * h0s[r * HID + k];
        h1s[nn * HID + k] = fmaxf(s, 0.f);
    }
    __syncthreads();

    #pragma unroll
    for (int nn = 0; nn < NN; nn++) acc[nn] = 0.f;
    for (int c = 0; c < HID; c++) {
        float wv = W2[c * HID + k];
        #pragma unroll
        for (int nn = 0; nn < NN; nn++) acc[nn] += h1s[nn * HID + c] * wv;
    }
    #pragma unroll
    for (int nn = 0; nn < NN; nn++) h0s[nn * HID + k] = acc[nn];
    __syncthreads();
    bv = b2[k];
    #pragma unroll
    for (int nn = 0; nn < NN; nn++) {
        float s = bv;
        #pragma unroll
        for (int r = 0; r < NN; r++) s += A[nn * NN + r] * h0s[r * HID + k];
        d_H[(t * NN + nn) * HID + k] = fmaxf(s, 0.f);
    }
}

// ---------------- shared input-gate precompute (pre-splat, 256 thr) ------
// G1[n][p][4k+g] = (bih1+bhh1)[g*128+k] + (Wih1 @ H[p-15])[g*128+k]
__global__ __launch_bounds__(256) void g1_kernel(
    const float* __restrict__ bih1, const float* __restrict__ bhh1) {
    int n = blockIdx.x, pc = blockIdx.y, tid = threadIdx.x;
    const int k = tid & 127, hf = tid >> 7, wbase = hf * 16;
    __shared__ float hs[HID * HSG];             // [kk][w], 32 windows
    for (int idx = tid; idx < 32 * HID; idx += 256) {
        int w = idx >> 7, kk = idx & 127;
        int p = pc * 32 + w;
        hs[kk * HSG + w] = (p >= 15 && p < 143)
                         ? d_H[((p - 15) * NN + n) * HID + kk] : 0.f;
    }
    __syncthreads();

    ull acc[4][8];
    #pragma unroll
    for (int g = 0; g < 4; g++) {
        ull b = splat2(bih1[n * G4 + g * HID + k] + bhh1[n * G4 + g * HID + k]);
        #pragma unroll
        for (int q = 0; q < 8; q++) acc[g][q] = b;
    }
    const float* WT = d_Wih1T + (size_t)n * HID * WROW;
    #pragma unroll 2
    for (int kk = 0; kk < HID; kk++) {
        const ulonglong2* wp = (const ulonglong2*)(WT + kk * WROW + 8 * k);
        ulonglong2 wa = wp[0], wb = wp[1];      // w0=wa.x w1=wa.y w2=wb.x w3=wb.y
        const ulonglong2* hv = (const ulonglong2*)(hs + kk * HSG + wbase);
        #pragma unroll
        for (int q2 = 0; q2 < 4; q2++) {
            ulonglong2 v = hv[q2];
            ffma2(acc[0][2 * q2],     wa.x, v.x); ffma2(acc[1][2 * q2],     wa.y, v.x);
            ffma2(acc[2][2 * q2],     wb.x, v.x); ffma2(acc[3][2 * q2],     wb.y, v.x);
            ffma2(acc[0][2 * q2 + 1], wa.x, v.y); ffma2(acc[1][2 * q2 + 1], wa.y, v.y);
            ffma2(acc[2][2 * q2 + 1], wb.x, v.y); ffma2(acc[3][2 * q2 + 1], wb.y, v.y);
        }
    }
    #pragma unroll
    for (int q = 0; q < 8; q++) {
        float2 u0 = unpack2(acc[0][q]), u1 = unpack2(acc[1][q]);
        float2 u2 = unpack2(acc[2][q]), u3 = unpack2(acc[3][q]);
        int p = pc * 32 + wbase + 2 * q;
        if (p < 143)
            *(float4*)(d_G1 + ((size_t)n * PPAD + p) * G4 + 4 * k)
                = make_float4(u0.x, u1.x, u2.x, u3.x);
        if (p + 1 < 143)
            *(float4*)(d_G1 + ((size_t)n * PPAD + p + 1) * G4 + 4 * k)
                = make_float4(u0.y, u1.y, u2.y, u3.y);
    }
}

// ---------------- stacked LSTM: double-buffered, 1 sync per step --------
__global__ __launch_bounds__(256, 2) void lstm_kernel(
    const float* __restrict__ bih2, const float* __restrict__ bhh2,
    const float* __restrict__ bfc,
    const float* __restrict__ Wout0, const float* __restrict__ bout0,
    const float* __restrict__ Wout1, const float* __restrict__ bout1,
    float* __restrict__ out) {
    int n = blockIdx.y, t0 = blockIdx.x * WPC, tid = threadIdx.x;
    const int k = tid & 127, hf = tid >> 7;
    const int wbase = hf * 8;
    __shared__ float h1s[2][HID * HS], h2s[2][HID * HS];   // ping-pong

    for (int i = tid; i < HID * HS; i += 256) {
        h1s[0][i] = 0.f; h1s[1][i] = 0.f;
        h2s[0][i] = 0.f; h2s[1][i] = 0.f;
    }

    ull bi2[4];
    #pragma unroll
    for (int g = 0; g < 4; g++)
        bi2[g] = splat2(bih2[n * G4 + g * HID + k] + bhh2[n * G4 + g * HID + k]);

    float c1[8], c2[8];
    #pragma unroll
    for (int w = 0; w < 8; w++) { c1[w] = 0.f; c2[w] = 0.f; }

    const float* Wh1 = d_Whh1T + (size_t)n * HID * WROW;
    const float* Wi2 = d_Wih2T + (size_t)n * HID * WROW;
    const float* Wh2 = d_Whh2T + (size_t)n * HID * WROW;
    const float* G1n = d_G1 + (size_t)n * PPAD * G4;
    __syncthreads();

    for (int l = 0; l < SEQL; l++) {
        const int rd = l & 1, wr = rd ^ 1;
        // ---- LSTM1: gates = G1[t0+w+l] + Whh1 @ h1[rd] ----
        ull acc[4][4];
        #pragma unroll
        for (int q = 0; q < 4; q++) {
            int p0 = t0 + wbase + 2 * q + l;
            float4 A = *(const float4*)(G1n + (size_t)p0 * G4 + 4 * k);
            float4 B = *(const float4*)(G1n + (size_t)(p0 + 1) * G4 + 4 * k);
            acc[0][q] = pack2(A.x, B.x); acc[1][q] = pack2(A.y, B.y);
            acc[2][q] = pack2(A.z, B.z); acc[3][q] = pack2(A.w, B.w);
        }
        #pragma unroll 4
        for (int kk = 0; kk < HID; kk++) {
            const ulonglong2* wp = (const ulonglong2*)(Wh1 + kk * WROW + 8 * k);
            ulonglong2 wa = wp[0], wb = wp[1];
            const ulonglong2* hv = (const ulonglong2*)(h1s[rd] + kk * HS + wbase);
            ulonglong2 v0 = hv[0], v1 = hv[1];
            ffma2(acc[0][0], wa.x, v0.x); ffma2(acc[1][0], wa.y, v0.x);
            ffma2(acc[2][0], wb.x, v0.x); ffma2(acc[3][0], wb.y, v0.x);
            ffma2(acc[0][1], wa.x, v0.y); ffma2(acc[1][1], wa.y, v0.y);
            ffma2(acc[2][1], wb.x, v0.y); ffma2(acc[3][1], wb.y, v0.y);
            ffma2(acc[0][2], wa.x, v1.x); ffma2(acc[1][2], wa.y, v1.x);
            ffma2(acc[2][2], wb.x, v1.x); ffma2(acc[3][2], wb.y, v1.x);
            ffma2(acc[0][3], wa.x, v1.y); ffma2(acc[1][3], wa.y, v1.y);
            ffma2(acc[2][3], wb.x, v1.y); ffma2(acc[3][3], wb.y, v1.y);
        }
        {   // cell1 -> write h1s[wr] (no barrier: readers used h1s[rd])
            float hrow[8];
            #pragma unroll
            for (int q = 0; q < 4; q++) {
                float2 iv = unpack2(acc[0][q]), fv = unpack2(acc[1][q]);
                float2 gv = unpack2(acc[2][q]), ov = unpack2(acc[3][q]);
                float c;
                c = sigf(fv.x) * c1[2 * q]     + sigf(iv.x) * tanh_f(gv.x);
                c1[2 * q] = c;     hrow[2 * q]     = sigf(ov.x) * tanh_f(c);
                c = sigf(fv.y) * c1[2 * q + 1] + sigf(iv.y) * tanh_f(gv.y);
                c1[2 * q + 1] = c; hrow[2 * q + 1] = sigf(ov.y) * tanh_f(c);
            }
            *(float4*)(h1s[wr] + k * HS + wbase)     = make_float4(hrow[0], hrow[1], hrow[2], hrow[3]);
            *(float4*)(h1s[wr] + k * HS + wbase + 4) = make_float4(hrow[4], hrow[5], hrow[6], hrow[7]);
        }
        __syncthreads();                       // the ONE barrier per step

        // ---- LSTM2: gates = bias2 + Wih2 @ h1[wr] + Whh2 @ h2[rd] ----
        #pragma unroll
        for (int g = 0; g < 4; g++) {
            #pragma unroll
            for (int q = 0; q < 4; q++) acc[g][q] = bi2[g];
        }
        #pragma unroll 2
        for (int kk = 0; kk < HID; kk++) {
            const ulonglong2* wip = (const ulonglong2*)(Wi2 + kk * WROW + 8 * k);
            const ulonglong2* whp = (const ulonglong2*)(Wh2 + kk * WROW + 8 * k);
            ulonglong2 ia = wip[0], ib = wip[1];
            ulonglong2 ha = whp[0], hb = whp[1];
            const ulonglong2* hv1 = (const ulonglong2*)(h1s[wr] + kk * HS + wbase);
            const ulonglong2* hv2 = (const ulonglong2*)(h2s[rd] + kk * HS + wbase);
            ulonglong2 a0 = hv1[0], a1 = hv1[1], b0 = hv2[0], b1 = hv2[1];
            ffma2(acc[0][0], ia.x, a0.x); ffma2(acc[1][0], ia.y, a0.x);
            ffma2(acc[2][0], ib.x, a0.x); ffma2(acc[3][0], ib.y, a0.x);
            ffma2(acc[0][0], ha.x, b0.x); ffma2(acc[1][0], ha.y, b0.x);
            ffma2(acc[2][0], hb.x, b0.x); ffma2(acc[3][0], hb.y, b0.x);
            ffma2(acc[0][1], ia.x, a0.y); ffma2(acc[1][1], ia.y, a0.y);
            ffma2(acc[2][1], ib.x, a0.y); ffma2(acc[3][1], ib.y, a0.y);
            ffma2(acc[0][1], ha.x, b0.y); ffma2(acc[1][1], ha.y, b0.y);
            ffma2(acc[2][1], hb.x, b0.y); ffma2(acc[3][1], hb.y, b0.y);
            ffma2(acc[0][2], ia.x, a1.x); ffma2(acc[1][2], ia.y, a1.x);
            ffma2(acc[2][2], ib.x, a1.x); ffma2(acc[3][2], ib.y, a1.x);
            ffma2(acc[0][2], ha.x, b1.x); ffma2(acc[1][2], ha.y, b1.x);
            ffma2(acc[2][2], hb.x, b1.x); ffma2(acc[3][2], hb.y, b1.x);
            ffma2(acc[0][3], ia.x, a1.y); ffma2(acc[1][3], ia.y, a1.y);
            ffma2(acc[2][3], ib.x, a1.y); ffma2(acc[3][3], ib.y, a1.y);
            ffma2(acc[0][3], ha.x, b1.y); ffma2(acc[1][3], ha.y, b1.y);
            ffma2(acc[2][3], hb.x, b1.y); ffma2(acc[3][3], hb.y, b1.y);
        }
        {   // cell2 -> write h2s[wr] (no barrier: readers used h2s[rd])
            float hrow[8];
            #pragma unroll
            for (int q = 0; q < 4; q++) {
                float2 iv = unpack2(acc[0][q]), fv = unpack2(acc[1][q]);
                float2 gv = unpack2(acc[2][q]), ov = unpack2(acc[3][q]);
                float c;
                c = sigf(fv.x) * c2[2 * q]     + sigf(iv.x) * tanh_f(gv.x);
                c2[2 * q] = c;     hrow[2 * q]     = sigf(ov.x) * tanh_f(c);
                c = sigf(fv.y) * c2[2 * q + 1] + sigf(iv.y) * tanh_f(gv.y);
                c2[2 * q + 1] = c; hrow[2 * q + 1] = sigf(ov.y) * tanh_f(c);
            }
            *(float4*)(h2s[wr] + k * HS + wbase)     = make_float4(hrow[0], hrow[1], hrow[2], hrow[3]);
            *(float4*)(h2s[wr] + k * HS + wbase + 4) = make_float4(hrow[4], hrow[5], hrow[6], hrow[7]);
        }
    }
    __syncthreads();
    // final h2 is in h2s[0] (l=15: wr = 0)

    // ---- epilogue: last = relu(h2); fc = last@WfcT + bfc; two heads ----
    for (int i = tid; i < HID * HS; i += 256) h1s[0][i] = fmaxf(h2s[0][i], 0.f);
    __syncthreads();
    {
        ull facc[4];
        ull bv = splat2(bfc[n * HID + k]);
        #pragma unroll
        for (int q = 0; q < 4; q++) facc[q] = bv;
        const float* WfT = d_WfcT + (size_t)n * HID * HID;
        #pragma unroll 2
        for (int h = 0; h < HID; h++) {
            ull wv = splat2(WfT[h * HID + k]);
            const ulonglong2* hv = (const ulonglong2*)(h1s[0] + h * HS + wbase);
            ulonglong2 v0 = hv[0], v1 = hv[1];
            ffma2(facc[0], wv, v0.x); ffma2(facc[1], wv, v0.y);
            ffma2(facc[2], wv, v1.x); ffma2(facc[3], wv, v1.y);
        }
        __syncthreads();
        #pragma unroll
        for (int q = 0; q < 4; q++) {
            float2 u = unpack2(facc[q]);
            h2s[0][k * HS + wbase + 2 * q]     = u.x;
            h2s[0][k * HS + wbase + 2 * q + 1] = u.y;
        }
    }
    __syncthreads();
    if (tid < WPC * 6) {
        int w = tid / 6, jj = tid % 6;
        const float* Wp; float bb;
        if (jj < 4) { Wp = Wout0 + n * 4 * HID + jj * HID;       bb = bout0[n * 4 + jj]; }
        else        { Wp = Wout1 + n * 2 * HID + (jj - 4) * HID; bb = bout1[n * 2 + (jj - 4)]; }
        float s = bb;
        #pragma unroll 4
        for (int kk = 0; kk < HID; kk++) s += Wp[kk] * h2s[0][kk * HS + w];
        int t = t0 + w;
        if (jj < 4) out[(t * NN + n) * 4 + jj] = s;
        else        out[T_STEPS * NN * 4 + (t * NN + n) * 2 + (jj - 4)] = s;
    }
}

// ------------------------------------------------------------------------
extern "C" void kernel_launch(void* const* d_in, const int* in_sizes, int n_in,
                              void* d_out, int out_size) {
    const float* x     = (const float*)d_in[0];
    const int*   ei    = (const int*)  d_in[1];
    const float* y     = (const float*)d_in[3];
    const float* W1    = (const float*)d_in[4];
    const float* b1    = (const float*)d_in[5];
    const float* W2    = (const float*)d_in[6];
    const float* b2    = (const float*)d_in[7];
    const float* Wih1  = (const float*)d_in[8];
    const float* Whh1  = (const float*)d_in[9];
    const float* bih1  = (const float*)d_in[10];
    const float* bhh1  = (const float*)d_in[11];
    const float* Wih2  = (const float*)d_in[12];
    const float* Whh2  = (const float*)d_in[13];
    const float* bih2  = (const float*)d_in[14];
    const float* bhh2  = (const float*)d_in[15];
    const float* Wfc   = (const float*)d_in[16];
    const float* bfc   = (const float*)d_in[17];
    const float* Wout0 = (const float*)d_in[18];
    const float* bout0 = (const float*)d_in[19];
    const float* Wout1 = (const float*)d_in[20];
    const float* bout1 = (const float*)d_in[21];
    float* out = (float*)d_out;

    transpose_kernel<<<dim3(32, 5), 256>>>(Wih1, Whh1, Wih2, Whh2, Wfc);
    gcn_kernel<<<128, 128>>>(x, ei, W1, b1, W2, b2);
    g1_kernel<<<dim3(32, 5), 256>>>(bih1, bhh1);
    lstm_kernel<<<dim3(8, 32), 256>>>(bih2, bhh2, bfc, Wout0, bout0, Wout1, bout1, out);

    cudaMemcpyAsync(out + T_STEPS * NN * 4 + T_STEPS * NN * 2, y,
                    T_STEPS * NN * 4 * sizeof(float), cudaMemcpyDeviceToDevice);
}

// round 6
// speedup vs baseline: 1.2058x; 1.2058x over previous
#include <cuda_runtime.h>
#include <math.h>

#define T_STEPS 128
#define NN 32
#define EE 512
#define INC 64
#define HID 128
#define SEQL 16
#define G4 512          // 4*HID
#define WPC 32          // windows per LSTM CTA (8 per quarter-group)
#define PPAD 144        // padded G1 rows (need 143 = T + SEQL - 1)
#define HS 36           // lstm smem row stride (floats): 16B-aligned, 32 windows
#define HSG 20          // g1 smem row stride (16 windows + pad)

typedef unsigned long long ull;

// ---------------- global scratch (no allocation allowed) ----------------
__device__ float d_H[T_STEPS * NN * HID];           // GCN output  [t][n][k]
__device__ float d_G1[NN * PPAD * G4];              // [n][p][4*k+g]
__device__ float d_Wih1T[NN * HID * G4];            // [n][kk][4*k+g], row j=g*128+k
__device__ float d_Whh1T[NN * HID * G4];
__device__ float d_Wih2T[NN * HID * G4];
__device__ float d_Whh2T[NN * HID * G4];
__device__ float d_WfcT[NN * HID * HID];            // [n][h][k2]

// ---------------- f32x2 packed helpers ----------------------------------
__device__ __forceinline__ void ffma2(ull &d, ull a, ull b) {
    asm("fma.rn.f32x2 %0, %1, %2, %0;" : "+l"(d) : "l"(a), "l"(b));
}
__device__ __forceinline__ ull splat2(float x) {
    ull r; unsigned u = __float_as_uint(x);
    asm("mov.b64 %0, {%1, %1};" : "=l"(r) : "r"(u)); return r;
}
__device__ __forceinline__ ull pack2(float x, float y) {
    ull r; unsigned a = __float_as_uint(x), b = __float_as_uint(y);
    asm("mov.b64 %0, {%1, %2};" : "=l"(r) : "r"(a), "r"(b)); return r;
}
__device__ __forceinline__ float2 unpack2(ull v) {
    unsigned a, b;
    asm("mov.b64 {%0, %1}, %2;" : "=r"(a), "=r"(b) : "l"(v));
    return make_float2(__uint_as_float(a), __uint_as_float(b));
}

// ---------------- fast transcendentals (rel err ~1e-6, tol 1e-3) --------
__device__ __forceinline__ float sigf(float x) {
    return __fdividef(1.0f, 1.0f + __expf(-x));
}
__device__ __forceinline__ float tanh_f(float x) {
    float ax = fabsf(x);
    float e  = __expf(-2.0f * ax);             // in (0,1], no overflow
    float t  = __fdividef(1.0f - e, 1.0f + e);
    return copysignf(t, x);
}

// ---------------- weight transposes (compact 4-gate layout) -------------
// LSTM mats: dst[n][kk*512 + 4*(j&127) + (j>>7)] = src[n][j][kk]
__global__ void transpose_kernel(const float* __restrict__ Wih1,
                                 const float* __restrict__ Whh1,
                                 const float* __restrict__ Wih2,
                                 const float* __restrict__ Whh2,
                                 const float* __restrict__ Wfc) {
    int n = blockIdx.x, m = blockIdx.y;
    __shared__ float s[32][33];
    int tx = threadIdx.x & 31, ty = threadIdx.x >> 5;   // 256 threads
    if (m == 4) {
        const float* src = Wfc + (size_t)n * HID * HID;
        float* dst = d_WfcT + (size_t)n * HID * HID;
        for (int bi = 0; bi < HID; bi += 32)
            for (int bj = 0; bj < HID; bj += 32) {
                #pragma unroll
                for (int r = ty; r < 32; r += 8)
                    s[r][tx] = src[(bi + r) * HID + bj + tx];
                __syncthreads();
                #pragma unroll
                for (int r = ty; r < 32; r += 8)
                    dst[(bj + r) * HID + bi + tx] = s[tx][r];
                __syncthreads();
            }
        return;
    }
    const float* src;
    float* dst;
    if      (m == 0) { src = Wih1; dst = d_Wih1T; }
    else if (m == 1) { src = Whh1; dst = d_Whh1T; }
    else if (m == 2) { src = Wih2; dst = d_Wih2T; }
    else             { src = Whh2; dst = d_Whh2T; }
    src += (size_t)n * G4 * HID; dst += (size_t)n * HID * G4;
    for (int bj = 0; bj < G4; bj += 32) {       // j blocks
        for (int bi = 0; bi < HID; bi += 32) {  // kk blocks
            #pragma unroll
            for (int r = ty; r < 32; r += 8)
                s[r][tx] = src[(bj + r) * HID + bi + tx];
            __syncthreads();
            #pragma unroll
            for (int r = ty; r < 32; r += 8) {
                int j = bj + tx;
                dst[(bi + r) * G4 + 4 * (j & 127) + (j >> 7)] = s[tx][r];
            }
            __syncthreads();
        }
    }
}

// ---------------- per-timestep 2-layer GCN ------------------------------
__global__ __launch_bounds__(128) void gcn_kernel(
    const float* __restrict__ x, const int* __restrict__ ei,
    const float* __restrict__ W1, const float* __restrict__ b1,
    const float* __restrict__ W2, const float* __restrict__ b2) {
    int t = blockIdx.x, k = threadIdx.x;
    __shared__ float xs[NN * INC];
    __shared__ float A[NN * NN];
    __shared__ float dinv[NN];
    __shared__ float h0s[NN * HID];
    __shared__ float h1s[NN * HID];

    for (int i = k; i < NN * INC; i += 128) xs[i] = x[t * NN * INC + i];
    for (int i = k; i < NN * NN; i += 128)  A[i] = 0.f;
    if (k < NN) dinv[k] = 1.0f;
    __syncthreads();

    const int* row = ei + t * 2 * EE;
    const int* col = row + EE;
    for (int e = k; e < EE; e += 128) atomicAdd(&dinv[col[e]], 1.0f);
    __syncthreads();
    if (k < NN) dinv[k] = rsqrtf(dinv[k]);
    __syncthreads();
    for (int e = k; e < EE; e += 128) {
        int r = row[e], c = col[e];
        atomicAdd(&A[c * NN + r], dinv[r] * dinv[c]);
    }
    if (k < NN) atomicAdd(&A[k * NN + k], dinv[k] * dinv[k]);
    __syncthreads();

    float acc[NN];
    #pragma unroll
    for (int nn = 0; nn < NN; nn++) acc[nn] = 0.f;
    for (int c = 0; c < INC; c++) {
        float wv = W1[c * HID + k];
        #pragma unroll
        for (int nn = 0; nn < NN; nn++) acc[nn] += xs[nn * INC + c] * wv;
    }
    #pragma unroll
    for (int nn = 0; nn < NN; nn++) h0s[nn * HID + k] = acc[nn];
    __syncthreads();
    float bv = b1[k];
    #pragma unroll
    for (int nn = 0; nn < NN; nn++) {
        float s = bv;
        #pragma unroll
        for (int r = 0; r < NN; r++) s += A[nn * NN + r] * h0s[r * HID + k];
        h1s[nn * HID + k] = fmaxf(s, 0.f);
    }
    __syncthreads();

    #pragma unroll
    for (int nn = 0; nn < NN; nn++) acc[nn] = 0.f;
    for (int c = 0; c < HID; c++) {
        float wv = W2[c * HID + k];
        #pragma unroll
        for (int nn = 0; nn < NN; nn++) acc[nn] += h1s[nn * HID + c] * wv;
    }
    #pragma unroll
    for (int nn = 0; nn < NN; nn++) h0s[nn * HID + k] = acc[nn];
    __syncthreads();
    bv = b2[k];
    #pragma unroll
    for (int nn = 0; nn < NN; nn++) {
        float s = bv;
        #pragma unroll
        for (int r = 0; r < NN; r++) s += A[nn * NN + r] * h0s[r * HID + k];
        d_H[(t * NN + nn) * HID + k] = fmaxf(s, 0.f);
    }
}

// ---------------- shared input-gate precompute (4-gate f32x2) ------------
// G1[n][p][4k+g] = (bih1+bhh1)[g*128+k] + (Wih1 @ H[p-15])[g*128+k]
__global__ __launch_bounds__(128) void g1_kernel(
    const float* __restrict__ bih1, const float* __restrict__ bhh1) {
    int n = blockIdx.x, pc = blockIdx.y, k = threadIdx.x;   // 16 windows/CTA
    __shared__ float hs[HID * HSG];             // [kk][w], 16 windows
    for (int idx = k; idx < 16 * HID; idx += 128) {
        int w = idx >> 7, kk = idx & 127;
        int p = pc * 16 + w;
        hs[kk * HSG + w] = (p >= 15 && p < 143)
                        ? d_H[((p - 15) * NN + n) * HID + kk] : 0.f;
    }
    __syncthreads();

    ull acc[4][8];
    #pragma unroll
    for (int g = 0; g < 4; g++) {
        ull b = splat2(bih1[n * G4 + g * HID + k] + bhh1[n * G4 + g * HID + k]);
        #pragma unroll
        for (int q = 0; q < 8; q++) acc[g][q] = b;
    }
    const float* WT = d_Wih1T + (size_t)n * HID * G4;
    #pragma unroll 2
    for (int kk = 0; kk < HID; kk++) {
        float4 wv = *(const float4*)(WT + kk * G4 + 4 * k);
        ull w0 = splat2(wv.x), w1 = splat2(wv.y), w2 = splat2(wv.z), w3 = splat2(wv.w);
        const ulonglong2* hv = (const ulonglong2*)(hs + kk * HSG);
        #pragma unroll
        for (int q2 = 0; q2 < 4; q2++) {
            ulonglong2 v = hv[q2];
            ffma2(acc[0][2 * q2],     w0, v.x); ffma2(acc[1][2 * q2],     w1, v.x);
            ffma2(acc[2][2 * q2],     w2, v.x); ffma2(acc[3][2 * q2],     w3, v.x);
            ffma2(acc[0][2 * q2 + 1], w0, v.y); ffma2(acc[1][2 * q2 + 1], w1, v.y);
            ffma2(acc[2][2 * q2 + 1], w2, v.y); ffma2(acc[3][2 * q2 + 1], w3, v.y);
        }
    }
    #pragma unroll
    for (int q = 0; q < 8; q++) {
        float2 u0 = unpack2(acc[0][q]), u1 = unpack2(acc[1][q]);
        float2 u2 = unpack2(acc[2][q]), u3 = unpack2(acc[3][q]);
        int p = pc * 16 + 2 * q;
        if (p < 143)
            *(float4*)(d_G1 + ((size_t)n * PPAD + p) * G4 + 4 * k)
                = make_float4(u0.x, u1.x, u2.x, u3.x);
        if (p + 1 < 143)
            *(float4*)(d_G1 + ((size_t)n * PPAD + p + 1) * G4 + 4 * k)
                = make_float4(u0.y, u1.y, u2.y, u3.y);
    }
}

// ---------------- stacked LSTM: 512 thr, 32 windows, double-buffered ----
__global__ __launch_bounds__(512, 1) void lstm_kernel(
    const float* __restrict__ bih2, const float* __restrict__ bhh2,
    const float* __restrict__ bfc,
    const float* __restrict__ Wout0, const float* __restrict__ bout0,
    const float* __restrict__ Wout1, const float* __restrict__ bout1,
    float* __restrict__ out) {
    int n = blockIdx.y, t0 = blockIdx.x * WPC, tid = threadIdx.x;
    const int k = tid & 127, hf = tid >> 7;     // quarter-group 0..3
    const int wbase = hf * 8;
    extern __shared__ float sm[];
    float* h1b[2] = { sm,                sm + HID * HS };
    float* h2b[2] = { sm + 2 * HID * HS, sm + 3 * HID * HS };

    for (int i = tid; i < 4 * HID * HS; i += 512) sm[i] = 0.f;

    ull bi2[4];
    #pragma unroll
    for (int g = 0; g < 4; g++)
        bi2[g] = splat2(bih2[n * G4 + g * HID + k] + bhh2[n * G4 + g * HID + k]);

    float c1[8], c2[8];
    #pragma unroll
    for (int w = 0; w < 8; w++) { c1[w] = 0.f; c2[w] = 0.f; }

    const float* Wh1 = d_Whh1T + (size_t)n * HID * G4;
    const float* Wi2 = d_Wih2T + (size_t)n * HID * G4;
    const float* Wh2 = d_Whh2T + (size_t)n * HID * G4;
    const float* G1n = d_G1 + (size_t)n * PPAD * G4;
    __syncthreads();

    for (int l = 0; l < SEQL; l++) {
        const int rd = l & 1, wr = rd ^ 1;
        const float* h1r = h1b[rd]; float* h1w = h1b[wr];
        const float* h2r = h2b[rd]; float* h2w = h2b[wr];
        // ---- LSTM1: gates = G1[t0+w+l] + Whh1 @ h1[rd] ----
        ull acc[4][4];
        #pragma unroll
        for (int q = 0; q < 4; q++) {
            int p0 = t0 + wbase + 2 * q + l;
            float4 A = *(const float4*)(G1n + (size_t)p0 * G4 + 4 * k);
            float4 B = *(const float4*)(G1n + (size_t)(p0 + 1) * G4 + 4 * k);
            acc[0][q] = pack2(A.x, B.x); acc[1][q] = pack2(A.y, B.y);
            acc[2][q] = pack2(A.z, B.z); acc[3][q] = pack2(A.w, B.w);
        }
        #pragma unroll 4
        for (int kk = 0; kk < HID; kk++) {
            float4 wv = *(const float4*)(Wh1 + kk * G4 + 4 * k);
            ull w0 = splat2(wv.x), w1 = splat2(wv.y), w2 = splat2(wv.z), w3 = splat2(wv.w);
            const ulonglong2* hv = (const ulonglong2*)(h1r + kk * HS + wbase);
            ulonglong2 v0 = hv[0], v1 = hv[1];
            ffma2(acc[0][0], w0, v0.x); ffma2(acc[1][0], w1, v0.x);
            ffma2(acc[2][0], w2, v0.x); ffma2(acc[3][0], w3, v0.x);
            ffma2(acc[0][1], w0, v0.y); ffma2(acc[1][1], w1, v0.y);
            ffma2(acc[2][1], w2, v0.y); ffma2(acc[3][1], w3, v0.y);
            ffma2(acc[0][2], w0, v1.x); ffma2(acc[1][2], w1, v1.x);
            ffma2(acc[2][2], w2, v1.x); ffma2(acc[3][2], w3, v1.x);
            ffma2(acc[0][3], w0, v1.y); ffma2(acc[1][3], w1, v1.y);
            ffma2(acc[2][3], w2, v1.y); ffma2(acc[3][3], w3, v1.y);
        }
        {   // cell1 -> write h1[wr] (no barrier: readers used h1[rd])
            float hrow[8];
            #pragma unroll
            for (int q = 0; q < 4; q++) {
                float2 iv = unpack2(acc[0][q]), fv = unpack2(acc[1][q]);
                float2 gv = unpack2(acc[2][q]), ov = unpack2(acc[3][q]);
                float c;
                c = sigf(fv.x) * c1[2 * q]     + sigf(iv.x) * tanh_f(gv.x);
                c1[2 * q] = c;     hrow[2 * q]     = sigf(ov.x) * tanh_f(c);
                c = sigf(fv.y) * c1[2 * q + 1] + sigf(iv.y) * tanh_f(gv.y);
                c1[2 * q + 1] = c; hrow[2 * q + 1] = sigf(ov.y) * tanh_f(c);
            }
            *(float4*)(h1w + k * HS + wbase)     = make_float4(hrow[0], hrow[1], hrow[2], hrow[3]);
            *(float4*)(h1w + k * HS + wbase + 4) = make_float4(hrow[4], hrow[5], hrow[6], hrow[7]);
        }
        __syncthreads();                       // the ONE barrier per step

        // ---- LSTM2: gates = bias2 + Wih2 @ h1[wr] + Whh2 @ h2[rd] ----
        #pragma unroll
        for (int g = 0; g < 4; g++) {
            #pragma unroll
            for (int q = 0; q < 4; q++) acc[g][q] = bi2[g];
        }
        #pragma unroll 2
        for (int kk = 0; kk < HID; kk++) {
            float4 wiv = *(const float4*)(Wi2 + kk * G4 + 4 * k);
            float4 whv = *(const float4*)(Wh2 + kk * G4 + 4 * k);
            ull i0 = splat2(wiv.x), i1 = splat2(wiv.y), i2 = splat2(wiv.z), i3 = splat2(wiv.w);
            ull m0 = splat2(whv.x), m1 = splat2(whv.y), m2 = splat2(whv.z), m3 = splat2(whv.w);
            const ulonglong2* hv1 = (const ulonglong2*)(h1w + kk * HS + wbase);
            const ulonglong2* hv2 = (const ulonglong2*)(h2r + kk * HS + wbase);
            ulonglong2 a0 = hv1[0], a1 = hv1[1], b0 = hv2[0], b1 = hv2[1];
            ffma2(acc[0][0], i0, a0.x); ffma2(acc[1][0], i1, a0.x);
            ffma2(acc[2][0], i2, a0.x); ffma2(acc[3][0], i3, a0.x);
            ffma2(acc[0][0], m0, b0.x); ffma2(acc[1][0], m1, b0.x);
            ffma2(acc[2][0], m2, b0.x); ffma2(acc[3][0], m3, b0.x);
            ffma2(acc[0][1], i0, a0.y); ffma2(acc[1][1], i1, a0.y);
            ffma2(acc[2][1], i2, a0.y); ffma2(acc[3][1], i3, a0.y);
            ffma2(acc[0][1], m0, b0.y); ffma2(acc[1][1], m1, b0.y);
            ffma2(acc[2][1], m2, b0.y); ffma2(acc[3][1], m3, b0.y);
            ffma2(acc[0][2], i0, a1.x); ffma2(acc[1][2], i1, a1.x);
            ffma2(acc[2][2], i2, a1.x); ffma2(acc[3][2], i3, a1.x);
            ffma2(acc[0][2], m0, b1.x); ffma2(acc[1][2], m1, b1.x);
            ffma2(acc[2][2], m2, b1.x); ffma2(acc[3][2], m3, b1.x);
            ffma2(acc[0][3], i0, a1.y); ffma2(acc[1][3], i1, a1.y);
            ffma2(acc[2][3], i2, a1.y); ffma2(acc[3][3], i3, a1.y);
            ffma2(acc[0][3], m0, b1.y); ffma2(acc[1][3], m1, b1.y);
            ffma2(acc[2][3], m2, b1.y); ffma2(acc[3][3], m3, b1.y);
        }
        {   // cell2 -> write h2[wr] (no barrier: readers used h2[rd])
            float hrow[8];
            #pragma unroll
            for (int q = 0; q < 4; q++) {
                float2 iv = unpack2(acc[0][q]), fv = unpack2(acc[1][q]);
                float2 gv = unpack2(acc[2][q]), ov = unpack2(acc[3][q]);
                float c;
                c = sigf(fv.x) * c2[2 * q]     + sigf(iv.x) * tanh_f(gv.x);
                c2[2 * q] = c;     hrow[2 * q]     = sigf(ov.x) * tanh_f(c);
                c = sigf(fv.y) * c2[2 * q + 1] + sigf(iv.y) * tanh_f(gv.y);
                c2[2 * q + 1] = c; hrow[2 * q + 1] = sigf(ov.y) * tanh_f(c);
            }
            *(float4*)(h2w + k * HS + wbase)     = make_float4(hrow[0], hrow[1], hrow[2], hrow[3]);
            *(float4*)(h2w + k * HS + wbase + 4) = make_float4(hrow[4], hrow[5], hrow[6], hrow[7]);
        }
    }
    __syncthreads();
    // final h2 is in h2b[0] (l=15: wr = 0)

    // ---- epilogue: last = relu(h2); fc = last@WfcT + bfc; two heads ----
    float* relu_buf = h1b[0];
    float* fc_buf   = h2b[1];
    for (int i = tid; i < HID * HS; i += 512) relu_buf[i] = fmaxf(h2b[0][i], 0.f);
    __syncthreads();
    {
        ull facc[4];
        ull bv = splat2(bfc[n * HID + k]);
        #pragma unroll
        for (int q = 0; q < 4; q++) facc[q] = bv;
        const float* WfT = d_WfcT + (size_t)n * HID * HID;
        #pragma unroll 2
        for (int h = 0; h < HID; h++) {
            ull wv = splat2(WfT[h * HID + k]);
            const ulonglong2* hv = (const ulonglong2*)(relu_buf + h * HS + wbase);
            ulonglong2 v0 = hv[0], v1 = hv[1];
            ffma2(facc[0], wv, v0.x); ffma2(facc[1], wv, v0.y);
            ffma2(facc[2], wv, v1.x); ffma2(facc[3], wv, v1.y);
        }
        __syncthreads();
        #pragma unroll
        for (int q = 0; q < 4; q++) {
            float2 u = unpack2(facc[q]);
            fc_buf[k * HS + wbase + 2 * q]     = u.x;
            fc_buf[k * HS + wbase + 2 * q + 1] = u.y;
        }
    }
    __syncthreads();
    if (tid < WPC * 6) {
        int w = tid / 6, jj = tid % 6;
        const float* Wp; float bb;
        if (jj < 4) { Wp = Wout0 + n * 4 * HID + jj * HID;       bb = bout0[n * 4 + jj]; }
        else        { Wp = Wout1 + n * 2 * HID + (jj - 4) * HID; bb = bout1[n * 2 + (jj - 4)]; }
        float s = bb;
        #pragma unroll 4
        for (int kk = 0; kk < HID; kk++) s += Wp[kk] * fc_buf[kk * HS + w];
        int t = t0 + w;
        if (jj < 4) out[(t * NN + n) * 4 + jj] = s;
        else        out[T_STEPS * NN * 4 + (t * NN + n) * 2 + (jj - 4)] = s;
    }
}

// ------------------------------------------------------------------------
extern "C" void kernel_launch(void* const* d_in, const int* in_sizes, int n_in,
                              void* d_out, int out_size) {
    const float* x     = (const float*)d_in[0];
    const int*   ei    = (const int*)  d_in[1];
    const float* y     = (const float*)d_in[3];
    const float* W1    = (const float*)d_in[4];
    const float* b1    = (const float*)d_in[5];
    const float* W2    = (const float*)d_in[6];
    const float* b2    = (const float*)d_in[7];
    const float* Wih1  = (const float*)d_in[8];
    const float* Whh1  = (const float*)d_in[9];
    const float* bih1  = (const float*)d_in[10];
    const float* bhh1  = (const float*)d_in[11];
    const float* Wih2  = (const float*)d_in[12];
    const float* Whh2  = (const float*)d_in[13];
    const float* bih2  = (const float*)d_in[14];
    const float* bhh2  = (const float*)d_in[15];
    const float* Wfc   = (const float*)d_in[16];
    const float* bfc   = (const float*)d_in[17];
    const float* Wout0 = (const float*)d_in[18];
    const float* bout0 = (const float*)d_in[19];
    const float* Wout1 = (const float*)d_in[20];
    const float* bout1 = (const float*)d_in[21];
    float* out = (float*)d_out;

    static int smem_set = 0;
    const int lstm_smem = 4 * HID * HS * (int)sizeof(float);   // 73728 B
    if (!smem_set) {
        cudaFuncSetAttribute(lstm_kernel,
                             cudaFuncAttributeMaxDynamicSharedMemorySize, lstm_smem);
        smem_set = 1;
    }

    transpose_kernel<<<dim3(32, 5), 256>>>(Wih1, Whh1, Wih2, Whh2, Wfc);
    gcn_kernel<<<128, 128>>>(x, ei, W1, b1, W2, b2);
    g1_kernel<<<dim3(32, 9), 128>>>(bih1, bhh1);
    lstm_kernel<<<dim3(4, 32), 512, lstm_smem>>>(bih2, bhh2, bfc,
                                                 Wout0, bout0, Wout1, bout1, out);

    cudaMemcpyAsync(out + T_STEPS * NN * 4 + T_STEPS * NN * 2, y,
                    T_STEPS * NN * 4 * sizeof(float), cudaMemcpyDeviceToDevice);
}

// round 7
// speedup vs baseline: 1.4212x; 1.1787x over previous
#include <cuda_runtime.h>
#include <math.h>

#define T_STEPS 128
#define NN 32
#define EE 512
#define INC 64
#define HID 128
#define SEQL 16
#define G4 512          // 4*HID
#define WPC 16          // windows per LSTM CTA (8 per half-group)
#define PPAD 144        // padded G1 rows (need 143 = T + SEQL - 1)
#define HS 20           // lstm/g1 smem row stride (floats): 16B-aligned

typedef unsigned long long ull;

// ---------------- global scratch (no allocation allowed) ----------------
__device__ float d_H[T_STEPS * NN * HID];           // GCN output  [t][n][k]
__device__ float d_G1[NN * PPAD * G4];              // [n][p][4*k+g]
__device__ float d_Wih1T[NN * HID * G4];            // [n][kk][4*k+g], row j=g*128+k
__device__ float d_Whh1T[NN * HID * G4];
__device__ float d_Wih2T[NN * HID * G4];
__device__ float d_Whh2T[NN * HID * G4];
__device__ float d_WfcT[NN * HID * HID];            // [n][h][k2]

// ---------------- f32x2 packed helpers ----------------------------------
__device__ __forceinline__ void ffma2(ull &d, ull a, ull b) {
    asm("fma.rn.f32x2 %0, %1, %2, %0;" : "+l"(d) : "l"(a), "l"(b));
}
__device__ __forceinline__ ull splat2(float x) {
    ull r; unsigned u = __float_as_uint(x);
    asm("mov.b64 %0, {%1, %1};" : "=l"(r) : "r"(u)); return r;
}
__device__ __forceinline__ ull pack2(float x, float y) {
    ull r; unsigned a = __float_as_uint(x), b = __float_as_uint(y);
    asm("mov.b64 %0, {%1, %2};" : "=l"(r) : "r"(a), "r"(b)); return r;
}
__device__ __forceinline__ float2 unpack2(ull v) {
    unsigned a, b;
    asm("mov.b64 {%0, %1}, %2;" : "=r"(a), "=r"(b) : "l"(v));
    return make_float2(__uint_as_float(a), __uint_as_float(b));
}
__device__ __forceinline__ void group_bar(int id) {
    asm volatile("bar.sync %0, 128;" :: "r"(id) : "memory");
}

// ---------------- fast transcendentals (rel err ~1e-6, tol 1e-3) --------
__device__ __forceinline__ float sigf(float x) {
    return __fdividef(1.0f, 1.0f + __expf(-x));
}
__device__ __forceinline__ float tanh_f(float x) {
    float ax = fabsf(x);
    float e  = __expf(-2.0f * ax);             // in (0,1], no overflow
    float t  = __fdividef(1.0f - e, 1.0f + e);
    return copysignf(t, x);
}

// ---------------- weight transposes (compact 4-gate layout) -------------
// LSTM mats: dst[n][kk*512 + 4*(j&127) + (j>>7)] = src[n][j][kk]
__global__ void transpose_kernel(const float* __restrict__ Wih1,
                                 const float* __restrict__ Whh1,
                                 const float* __restrict__ Wih2,
                                 const float* __restrict__ Whh2,
                                 const float* __restrict__ Wfc) {
    int n = blockIdx.x, m = blockIdx.y;
    __shared__ float s[32][33];
    int tx = threadIdx.x & 31, ty = threadIdx.x >> 5;   // 256 threads
    if (m == 4) {
        const float* src = Wfc + (size_t)n * HID * HID;
        float* dst = d_WfcT + (size_t)n * HID * HID;
        for (int bi = 0; bi < HID; bi += 32)
            for (int bj = 0; bj < HID; bj += 32) {
                #pragma unroll
                for (int r = ty; r < 32; r += 8)
                    s[r][tx] = src[(bi + r) * HID + bj + tx];
                __syncthreads();
                #pragma unroll
                for (int r = ty; r < 32; r += 8)
                    dst[(bj + r) * HID + bi + tx] = s[tx][r];
                __syncthreads();
            }
        return;
    }
    const float* src;
    float* dst;
    if      (m == 0) { src = Wih1; dst = d_Wih1T; }
    else if (m == 1) { src = Whh1; dst = d_Whh1T; }
    else if (m == 2) { src = Wih2; dst = d_Wih2T; }
    else             { src = Whh2; dst = d_Whh2T; }
    src += (size_t)n * G4 * HID; dst += (size_t)n * HID * G4;
    for (int bj = 0; bj < G4; bj += 32) {       // j blocks
        for (int bi = 0; bi < HID; bi += 32) {  // kk blocks
            #pragma unroll
            for (int r = ty; r < 32; r += 8)
                s[r][tx] = src[(bj + r) * HID + bi + tx];
            __syncthreads();
            #pragma unroll
            for (int r = ty; r < 32; r += 8) {
                int j = bj + tx;
                dst[(bi + r) * G4 + 4 * (j & 127) + (j >> 7)] = s[tx][r];
            }
            __syncthreads();
        }
    }
}

// ---------------- per-timestep 2-layer GCN ------------------------------
__global__ __launch_bounds__(128) void gcn_kernel(
    const float* __restrict__ x, const int* __restrict__ ei,
    const float* __restrict__ W1, const float* __restrict__ b1,
    const float* __restrict__ W2, const float* __restrict__ b2) {
    int t = blockIdx.x, k = threadIdx.x;
    __shared__ float xs[NN * INC];
    __shared__ float A[NN * NN];
    __shared__ float dinv[NN];
    __shared__ float h0s[NN * HID];
    __shared__ float h1s[NN * HID];

    for (int i = k; i < NN * INC; i += 128) xs[i] = x[t * NN * INC + i];
    for (int i = k; i < NN * NN; i += 128)  A[i] = 0.f;
    if (k < NN) dinv[k] = 1.0f;
    __syncthreads();

    const int* row = ei + t * 2 * EE;
    const int* col = row + EE;
    for (int e = k; e < EE; e += 128) atomicAdd(&dinv[col[e]], 1.0f);
    __syncthreads();
    if (k < NN) dinv[k] = rsqrtf(dinv[k]);
    __syncthreads();
    for (int e = k; e < EE; e += 128) {
        int r = row[e], c = col[e];
        atomicAdd(&A[c * NN + r], dinv[r] * dinv[c]);
    }
    if (k < NN) atomicAdd(&A[k * NN + k], dinv[k] * dinv[k]);
    __syncthreads();

    float acc[NN];
    #pragma unroll
    for (int nn = 0; nn < NN; nn++) acc[nn] = 0.f;
    for (int c = 0; c < INC; c++) {
        float wv = W1[c * HID + k];
        #pragma unroll
        for (int nn = 0; nn < NN; nn++) acc[nn] += xs[nn * INC + c] * wv;
    }
    #pragma unroll
    for (int nn = 0; nn < NN; nn++) h0s[nn * HID + k] = acc[nn];
    __syncthreads();
    float bv = b1[k];
    #pragma unroll
    for (int nn = 0; nn < NN; nn++) {
        float s = bv;
        #pragma unroll
        for (int r = 0; r < NN; r++) s += A[nn * NN + r] * h0s[r * HID + k];
        h1s[nn * HID + k] = fmaxf(s, 0.f);
    }
    __syncthreads();

    #pragma unroll
    for (int nn = 0; nn < NN; nn++) acc[nn] = 0.f;
    for (int c = 0; c < HID; c++) {
        float wv = W2[c * HID + k];
        #pragma unroll
        for (int nn = 0; nn < NN; nn++) acc[nn] += h1s[nn * HID + c] * wv;
    }
    #pragma unroll
    for (int nn = 0; nn < NN; nn++) h0s[nn * HID + k] = acc[nn];
    __syncthreads();
    bv = b2[k];
    #pragma unroll
    for (int nn = 0; nn < NN; nn++) {
        float s = bv;
        #pragma unroll
        for (int r = 0; r < NN; r++) s += A[nn * NN + r] * h0s[r * HID + k];
        d_H[(t * NN + nn) * HID + k] = fmaxf(s, 0.f);
    }
}

// ---------------- shared input-gate precompute (4-gate f32x2) ------------
// G1[n][p][4k+g] = (bih1+bhh1)[g*128+k] + (Wih1 @ H[p-15])[g*128+k]
__global__ __launch_bounds__(128) void g1_kernel(
    const float* __restrict__ bih1, const float* __restrict__ bhh1) {
    int n = blockIdx.x, pc = blockIdx.y, k = threadIdx.x;   // 16 windows/CTA
    __shared__ float hs[HID * HS];              // [kk][w], 16 windows
    for (int idx = k; idx < 16 * HID; idx += 128) {
        int w = idx >> 7, kk = idx & 127;
        int p = pc * 16 + w;
        hs[kk * HS + w] = (p >= 15 && p < 143)
                        ? d_H[((p - 15) * NN + n) * HID + kk] : 0.f;
    }
    __syncthreads();

    ull acc[4][8];
    #pragma unroll
    for (int g = 0; g < 4; g++) {
        ull b = splat2(bih1[n * G4 + g * HID + k] + bhh1[n * G4 + g * HID + k]);
        #pragma unroll
        for (int q = 0; q < 8; q++) acc[g][q] = b;
    }
    const float* WT = d_Wih1T + (size_t)n * HID * G4;
    #pragma unroll 2
    for (int kk = 0; kk < HID; kk++) {
        float4 wv = *(const float4*)(WT + kk * G4 + 4 * k);
        ull w0 = splat2(wv.x), w1 = splat2(wv.y), w2 = splat2(wv.z), w3 = splat2(wv.w);
        const ulonglong2* hv = (const ulonglong2*)(hs + kk * HS);
        #pragma unroll
        for (int q2 = 0; q2 < 4; q2++) {
            ulonglong2 v = hv[q2];
            ffma2(acc[0][2 * q2],     w0, v.x); ffma2(acc[1][2 * q2],     w1, v.x);
            ffma2(acc[2][2 * q2],     w2, v.x); ffma2(acc[3][2 * q2],     w3, v.x);
            ffma2(acc[0][2 * q2 + 1], w0, v.y); ffma2(acc[1][2 * q2 + 1], w1, v.y);
            ffma2(acc[2][2 * q2 + 1], w2, v.y); ffma2(acc[3][2 * q2 + 1], w3, v.y);
        }
    }
    #pragma unroll
    for (int q = 0; q < 8; q++) {
        float2 u0 = unpack2(acc[0][q]), u1 = unpack2(acc[1][q]);
        float2 u2 = unpack2(acc[2][q]), u3 = unpack2(acc[3][q]);
        int p = pc * 16 + 2 * q;
        if (p < 143)
            *(float4*)(d_G1 + ((size_t)n * PPAD + p) * G4 + 4 * k)
                = make_float4(u0.x, u1.x, u2.x, u3.x);
        if (p + 1 < 143)
            *(float4*)(d_G1 + ((size_t)n * PPAD + p + 1) * G4 + 4 * k)
                = make_float4(u0.y, u1.y, u2.y, u3.y);
    }
}

// ---------------- stacked LSTM: independent half-groups, named barriers --
__global__ __launch_bounds__(256, 2) void lstm_kernel(
    const float* __restrict__ bih2, const float* __restrict__ bhh2,
    const float* __restrict__ bfc,
    const float* __restrict__ Wout0, const float* __restrict__ bout0,
    const float* __restrict__ Wout1, const float* __restrict__ bout1,
    float* __restrict__ out) {
    int n = blockIdx.y, t0 = blockIdx.x * WPC, tid = threadIdx.x;
    const int k = tid & 127, hf = tid >> 7;     // half-group 0/1
    const int wbase = hf * 8, bar = 1 + hf;
    __shared__ float h1s[2][HID * HS], h2s[2][HID * HS];   // ping-pong

    for (int i = tid; i < HID * HS; i += 256) {
        h1s[0][i] = 0.f; h1s[1][i] = 0.f;
        h2s[0][i] = 0.f; h2s[1][i] = 0.f;
    }

    ull bi2[4];
    #pragma unroll
    for (int g = 0; g < 4; g++)
        bi2[g] = splat2(bih2[n * G4 + g * HID + k] + bhh2[n * G4 + g * HID + k]);

    float c1[8], c2[8];
    #pragma unroll
    for (int w = 0; w < 8; w++) { c1[w] = 0.f; c2[w] = 0.f; }

    const float* Wh1 = d_Whh1T + (size_t)n * HID * G4;
    const float* Wi2 = d_Wih2T + (size_t)n * HID * G4;
    const float* Wh2 = d_Whh2T + (size_t)n * HID * G4;
    const float* G1n = d_G1 + (size_t)n * PPAD * G4;
    __syncthreads();            // smem-zero visible to both groups

    for (int l = 0; l < SEQL; l++) {
        const int rd = l & 1, wr = rd ^ 1;
        // ---- LSTM1: gates = G1[t0+w+l] + Whh1 @ h1[rd] ----
        ull acc[4][4];
        #pragma unroll
        for (int q = 0; q < 4; q++) {
            int p0 = t0 + wbase + 2 * q + l;
            float4 A = *(const float4*)(G1n + (size_t)p0 * G4 + 4 * k);
            float4 B = *(const float4*)(G1n + (size_t)(p0 + 1) * G4 + 4 * k);
            acc[0][q] = pack2(A.x, B.x); acc[1][q] = pack2(A.y, B.y);
            acc[2][q] = pack2(A.z, B.z); acc[3][q] = pack2(A.w, B.w);
        }
        #pragma unroll 4
        for (int kk = 0; kk < HID; kk++) {
            float4 wv = *(const float4*)(Wh1 + kk * G4 + 4 * k);
            ull w0 = splat2(wv.x), w1 = splat2(wv.y), w2 = splat2(wv.z), w3 = splat2(wv.w);
            const ulonglong2* hv = (const ulonglong2*)(h1s[rd] + kk * HS + wbase);
            ulonglong2 v0 = hv[0], v1 = hv[1];
            ffma2(acc[0][0], w0, v0.x); ffma2(acc[1][0], w1, v0.x);
            ffma2(acc[2][0], w2, v0.x); ffma2(acc[3][0], w3, v0.x);
            ffma2(acc[0][1], w0, v0.y); ffma2(acc[1][1], w1, v0.y);
            ffma2(acc[2][1], w2, v0.y); ffma2(acc[3][1], w3, v0.y);
            ffma2(acc[0][2], w0, v1.x); ffma2(acc[1][2], w1, v1.x);
            ffma2(acc[2][2], w2, v1.x); ffma2(acc[3][2], w3, v1.x);
            ffma2(acc[0][3], w0, v1.y); ffma2(acc[1][3], w1, v1.y);
            ffma2(acc[2][3], w2, v1.y); ffma2(acc[3][3], w3, v1.y);
        }
        {   // cell1 -> write h1[wr] (own group's columns only)
            float hrow[8];
            #pragma unroll
            for (int q = 0; q < 4; q++) {
                float2 iv = unpack2(acc[0][q]), fv = unpack2(acc[1][q]);
                float2 gv = unpack2(acc[2][q]), ov = unpack2(acc[3][q]);
                float c;
                c = sigf(fv.x) * c1[2 * q]     + sigf(iv.x) * tanh_f(gv.x);
                c1[2 * q] = c;     hrow[2 * q]     = sigf(ov.x) * tanh_f(c);
                c = sigf(fv.y) * c1[2 * q + 1] + sigf(iv.y) * tanh_f(gv.y);
                c1[2 * q + 1] = c; hrow[2 * q + 1] = sigf(ov.y) * tanh_f(c);
            }
            *(float4*)(h1s[wr] + k * HS + wbase)     = make_float4(hrow[0], hrow[1], hrow[2], hrow[3]);
            *(float4*)(h1s[wr] + k * HS + wbase + 4) = make_float4(hrow[4], hrow[5], hrow[6], hrow[7]);
        }
        group_bar(bar);                        // half-group-scoped barrier

        // ---- LSTM2: gates = bias2 + Wih2 @ h1[wr] + Whh2 @ h2[rd] ----
        #pragma unroll
        for (int g = 0; g < 4; g++) {
            #pragma unroll
            for (int q = 0; q < 4; q++) acc[g][q] = bi2[g];
        }
        #pragma unroll 2
        for (int kk = 0; kk < HID; kk++) {
            float4 wiv = *(const float4*)(Wi2 + kk * G4 + 4 * k);
            float4 whv = *(const float4*)(Wh2 + kk * G4 + 4 * k);
            ull i0 = splat2(wiv.x), i1 = splat2(wiv.y), i2 = splat2(wiv.z), i3 = splat2(wiv.w);
            ull m0 = splat2(whv.x), m1 = splat2(whv.y), m2 = splat2(whv.z), m3 = splat2(whv.w);
            const ulonglong2* hv1 = (const ulonglong2*)(h1s[wr] + kk * HS + wbase);
            const ulonglong2* hv2 = (const ulonglong2*)(h2s[rd] + kk * HS + wbase);
            ulonglong2 a0 = hv1[0], a1 = hv1[1], b0 = hv2[0], b1 = hv2[1];
            ffma2(acc[0][0], i0, a0.x); ffma2(acc[1][0], i1, a0.x);
            ffma2(acc[2][0], i2, a0.x); ffma2(acc[3][0], i3, a0.x);
            ffma2(acc[0][0], m0, b0.x); ffma2(acc[1][0], m1, b0.x);
            ffma2(acc[2][0], m2, b0.x); ffma2(acc[3][0], m3, b0.x);
            ffma2(acc[0][1], i0, a0.y); ffma2(acc[1][1], i1, a0.y);
            ffma2(acc[2][1], i2, a0.y); ffma2(acc[3][1], i3, a0.y);
            ffma2(acc[0][1], m0, b0.y); ffma2(acc[1][1], m1, b0.y);
            ffma2(acc[2][1], m2, b0.y); ffma2(acc[3][1], m3, b0.y);
            ffma2(acc[0][2], i0, a1.x); ffma2(acc[1][2], i1, a1.x);
            ffma2(acc[2][2], i2, a1.x); ffma2(acc[3][2], i3, a1.x);
            ffma2(acc[0][2], m0, b1.x); ffma2(acc[1][2], m1, b1.x);
            ffma2(acc[2][2], m2, b1.x); ffma2(acc[3][2], m3, b1.x);
            ffma2(acc[0][3], i0, a1.y); ffma2(acc[1][3], i1, a1.y);
            ffma2(acc[2][3], i2, a1.y); ffma2(acc[3][3], i3, a1.y);
            ffma2(acc[0][3], m0, b1.y); ffma2(acc[1][3], m1, b1.y);
            ffma2(acc[2][3], m2, b1.y); ffma2(acc[3][3], m3, b1.y);
        }
        {   // cell2 -> write h2[wr] (own group's columns only)
            float hrow[8];
            #pragma unroll
            for (int q = 0; q < 4; q++) {
                float2 iv = unpack2(acc[0][q]), fv = unpack2(acc[1][q]);
                float2 gv = unpack2(acc[2][q]), ov = unpack2(acc[3][q]);
                float c;
                c = sigf(fv.x) * c2[2 * q]     + sigf(iv.x) * tanh_f(gv.x);
                c2[2 * q] = c;     hrow[2 * q]     = sigf(ov.x) * tanh_f(c);
                c = sigf(fv.y) * c2[2 * q + 1] + sigf(iv.y) * tanh_f(gv.y);
                c2[2 * q + 1] = c; hrow[2 * q + 1] = sigf(ov.y) * tanh_f(c);
            }
            *(float4*)(h2s[wr] + k * HS + wbase)     = make_float4(hrow[0], hrow[1], hrow[2], hrow[3]);
            *(float4*)(h2s[wr] + k * HS + wbase + 4) = make_float4(hrow[4], hrow[5], hrow[6], hrow[7]);
        }
        group_bar(bar);                        // order cell2 writes vs next GEMM2 reads
    }
    __syncthreads();
    // final h2 is in h2s[0] (l=15: wr = 0)

    // ---- epilogue: last = relu(h2); fc = last@WfcT + bfc; two heads ----
    for (int i = tid; i < HID * HS; i += 256) h1s[0][i] = fmaxf(h2s[0][i], 0.f);
    __syncthreads();
    {
        ull facc[4];
        ull bv = splat2(bfc[n * HID + k]);
        #pragma unroll
        for (int q = 0; q < 4; q++) facc[q] = bv;
        const float* WfT = d_WfcT + (size_t)n * HID * HID;
        #pragma unroll 2
        for (int h = 0; h < HID; h++) {
            ull wv = splat2(WfT[h * HID + k]);
            const ulonglong2* hv = (const ulonglong2*)(h1s[0] + h * HS + wbase);
            ulonglong2 v0 = hv[0], v1 = hv[1];
            ffma2(facc[0], wv, v0.x); ffma2(facc[1], wv, v0.y);
            ffma2(facc[2], wv, v1.x); ffma2(facc[3], wv, v1.y);
        }
        __syncthreads();
        #pragma unroll
        for (int q = 0; q < 4; q++) {
            float2 u = unpack2(facc[q]);
            h2s[0][k * HS + wbase + 2 * q]     = u.x;
            h2s[0][k * HS + wbase + 2 * q + 1] = u.y;
        }
    }
    __syncthreads();
    if (tid < WPC * 6) {
        int w = tid / 6, jj = tid % 6;
        const float* Wp; float bb;
        if (jj < 4) { Wp = Wout0 + n * 4 * HID + jj * HID;       bb = bout0[n * 4 + jj]; }
        else        { Wp = Wout1 + n * 2 * HID + (jj - 4) * HID; bb = bout1[n * 2 + (jj - 4)]; }
        float s = bb;
        #pragma unroll 4
        for (int kk = 0; kk < HID; kk++) s += Wp[kk] * h2s[0][kk * HS + w];
        int t = t0 + w;
        if (jj < 4) out[(t * NN + n) * 4 + jj] = s;
        else        out[T_STEPS * NN * 4 + (t * NN + n) * 2 + (jj - 4)] = s;
    }
}

// ------------------------------------------------------------------------
extern "C" void kernel_launch(void* const* d_in, const int* in_sizes, int n_in,
                              void* d_out, int out_size) {
    const float* x     = (const float*)d_in[0];
    const int*   ei    = (const int*)  d_in[1];
    const float* y     = (const float*)d_in[3];
    const float* W1    = (const float*)d_in[4];
    const float* b1    = (const float*)d_in[5];
    const float* W2    = (const float*)d_in[6];
    const float* b2    = (const float*)d_in[7];
    const float* Wih1  = (const float*)d_in[8];
    const float* Whh1  = (const float*)d_in[9];
    const float* bih1  = (const float*)d_in[10];
    const float* bhh1  = (const float*)d_in[11];
    const float* Wih2  = (const float*)d_in[12];
    const float* Whh2  = (const float*)d_in[13];
    const float* bih2  = (const float*)d_in[14];
    const float* bhh2  = (const float*)d_in[15];
    const float* Wfc   = (const float*)d_in[16];
    const float* bfc   = (const float*)d_in[17];
    const float* Wout0 = (const float*)d_in[18];
    const float* bout0 = (const float*)d_in[19];
    const float* Wout1 = (const float*)d_in[20];
    const float* bout1 = (const float*)d_in[21];
    float* out = (float*)d_out;

    transpose_kernel<<<dim3(32, 5), 256>>>(Wih1, Whh1, Wih2, Whh2, Wfc);
    gcn_kernel<<<128, 128>>>(x, ei, W1, b1, W2, b2);
    g1_kernel<<<dim3(32, 9), 128>>>(bih1, bhh1);
    lstm_kernel<<<dim3(8, 32), 256>>>(bih2, bhh2, bfc, Wout0, bout0, Wout1, bout1, out);

    cudaMemcpyAsync(out + T_STEPS * NN * 4 + T_STEPS * NN * 2, y,
                    T_STEPS * NN * 4 * sizeof(float), cudaMemcpyDeviceToDevice);
}